// round 11
// baseline (speedup 1.0000x reference)
#include <cuda_runtime.h>
#include <cuda_fp16.h>
#include <math.h>
#include <stdint.h>

// ---------------- problem constants ----------------
#define EPS    1e-6f
#define N_EP   2048
#define NS     5
#define SLOTS  13
#define D      256
#define NROW   16384
#define KEXT   512              // stored anchors: [hi(256) | lo(256)] fp16
#define MT     128              // M rows per CTA
#define NT     64               // N cols per tile
#define NTILES (N_EP / NT)      // 32
#define NKC    16               // k-steps of 16 over K=256 (hi only)
#define NTH    256
#define LOG2E  1.4426950408889634f
#define SC2    2.8853900817779268f   // 2*log2(e)
#define LN2    0.6931471805599453
#define SKIP_THR 24.0f

// ---------------- device globals ----------------
__device__ __align__(256) __half g_aext[N_EP * KEXT];  // anchors split [n][512]
__device__ __align__(256) float  g_cc2[N_EP];          // (-a_sq + 2*eps*a_sum)*log2e
__device__ double g_loss;
__device__ int    g_correct;
__device__ int    g_lab32;

// ---------------- smem layout (dynamic, bytes) ----------------
#define SM_CC    0          // 2048 floats = 8192
#define SM_A0    8192       // B tiles: 64 rows x 512B = 32768 each
#define SM_A1    40960
#define SM_A2    73728
#define SM_Q     40960      // Q staging (128 rows x 512B = 65536) aliases A1+A2
#define SMEM_BYTES 106496
// post-loop merge arrays alias buffer A0 (8192..40960)
#define SM_MRM   8192       // [128][2] float
#define SM_MRS   9216
#define SM_MBV   10240
#define SM_MBI   11264
#define SM_FM    12288      // [128] float
#define SM_FS    12800
#define SM_FBI   13312
#define SM_SD    13824      // [8] double
#define SM_SI    13888      // [8] int

// ---------------- PTX helpers (sm_80-level, portable to compute_103) --------
__device__ __forceinline__ uint32_t smem_u32(const void* p) {
    uint32_t a;
    asm("{ .reg .u64 t; cvta.to.shared.u64 t, %1; cvt.u32.u64 %0, t; }" : "=r"(a) : "l"(p));
    return a;
}
#define CP_ASYNC16(dst, src) \
    asm volatile("cp.async.cg.shared.global [%0], [%1], 16;" :: "r"(dst), "l"(src) : "memory")
#define CP_COMMIT() asm volatile("cp.async.commit_group;" ::: "memory")
#define CP_WAIT0()  asm volatile("cp.async.wait_group 0;" ::: "memory")
#define CP_WAIT1()  asm volatile("cp.async.wait_group 1;" ::: "memory")

#define LDSM_X4(r0, r1, r2, r3, addr) \
    asm volatile("ldmatrix.sync.aligned.m8n8.x4.shared.b16 {%0,%1,%2,%3}, [%4];" \
        : "=r"(r0), "=r"(r1), "=r"(r2), "=r"(r3) : "r"(addr))

#define MMA16816(c, a0, a1, a2, a3, b0, b1) \
    asm volatile("mma.sync.aligned.m16n8k16.row.col.f32.f16.f16.f32 " \
        "{%0,%1,%2,%3}, {%4,%5,%6,%7}, {%8,%9}, {%0,%1,%2,%3};" \
        : "+f"((c)[0]), "+f"((c)[1]), "+f"((c)[2]), "+f"((c)[3]) \
        : "r"(a0), "r"(a1), "r"(a2), "r"(a3), "r"(b0), "r"(b1))

__device__ __forceinline__ float ex2f(float x) { float r; asm("ex2.approx.f32 %0, %1;" : "=f"(r) : "f"(x)); return r; }
__device__ __forceinline__ float lg2f(float x) { float r; asm("lg2.approx.f32 %0, %1;" : "=f"(r) : "f"(x)); return r; }

// ---------------- prep: anchors split + column constant + init/label sniff --
__global__ void prep_kernel(const float* __restrict__ x,
                            const unsigned long long* __restrict__ lab) {
    int i = blockIdx.x;
    int d = threadIdx.x;                       // 256 threads == D
    if (i == 0 && d < 32) {                    // folded init
        unsigned long long v = lab[d];
        unsigned b = __ballot_sync(0xFFFFFFFFu, (v >> 32) != 0ull);
        if (d == 0) { g_loss = 0.0; g_correct = 0; g_lab32 = (b != 0u) ? 1 : 0; }
    }
    const float* xr = x + (size_t)i * SLOTS * D + d;
    float a = (xr[0] + xr[D] + xr[2 * D] + xr[3 * D] + xr[4 * D]) * 0.2f;

    __half hi = __float2half_rn(a);
    __half lo = __float2half_rn(a - __half2float(hi));
    g_aext[(size_t)i * KEXT + d]       = hi;   // hi half: used by GEMM
    g_aext[(size_t)i * KEXT + 256 + d] = lo;   // lo half: used by exact label dot

    float sq = a * a, sm = a;
#pragma unroll
    for (int o = 16; o; o >>= 1) {
        sq += __shfl_xor_sync(0xFFFFFFFFu, sq, o);
        sm += __shfl_xor_sync(0xFFFFFFFFu, sm, o);
    }
    __shared__ float ssq[8], ssm[8];
    if ((threadIdx.x & 31) == 0) { ssq[threadIdx.x >> 5] = sq; ssm[threadIdx.x >> 5] = sm; }
    __syncthreads();
    if (threadIdx.x == 0) {
        float t1 = 0.f, t2 = 0.f;
#pragma unroll
        for (int k = 0; k < 8; k++) { t1 += ssq[k]; t2 += ssm[k]; }
        g_cc2[i] = (-t1 + 2.0f * EPS * t2) * LOG2E;
    }
}

// ---------------- fused HMMA GEMM + online softmax + loss ---------------------
extern __shared__ char dsm[];

__global__ void __launch_bounds__(NTH, 1) gemm_softmax_kernel(
    const float* __restrict__ x, const void* __restrict__ labraw) {
    const uint32_t sb = smem_u32(dsm);
    const int tid = threadIdx.x, wid = tid >> 5, lane = tid & 31;
    const int qid = lane & 3, g = lane >> 2;
    const int wh = wid & 3;        // row group (32 rows)
    const int nh = wid >> 2;       // col half (32 cols)
    const int r0 = blockIdx.x * MT;

    // ---- issue A tile 0 early ----
    {
        const char* asrc = (const char*)g_aext;        // row stride 1024B; hi = first 512B
#pragma unroll
        for (int i = 0; i < 8; i++) {
            int f = i * NTH + tid;                     // 64 rows x 32 16B-chunks
            int row = f >> 5, c = f & 31;
            uint32_t dst = sb + SM_A0 + row * 512 + ((c ^ (row & 7)) << 4);
            CP_ASYNC16(dst, asrc + (size_t)row * 1024 + c * 16);
        }
        CP_COMMIT();
    }

    // ---- stage column constants ----
#pragma unroll
    for (int i = tid; i < N_EP / 4; i += NTH)
        ((float4*)(dsm + SM_CC))[i] = ((const float4*)g_cc2)[i];

    // ---- stage Q tile (fp32 -> fp16 hi only, 512B XOR-swizzled rows) ----
#pragma unroll 2
    for (int i = 0; i < 32; i++) {
        int f = i * NTH + tid;            // 128 rows x 64 float4-segments
        int row = f >> 6, seg = f & 63;
        int r = r0 + row;
        const float4 v = *(const float4*)(x + ((size_t)(r >> 3) * SLOTS + NS + (r & 7)) * D + seg * 4);
        __half2 ph01 = __halves2half2(__float2half_rn(v.x), __float2half_rn(v.y));
        __half2 ph23 = __halves2half2(__float2half_rn(v.z), __float2half_rn(v.w));
        unsigned long long uh = ((unsigned long long)(*(uint32_t*)&ph23) << 32) | (*(uint32_t*)&ph01);
        int rp = row & 7;
        int ch = seg >> 1;
        int sub = (seg & 1) * 8;
        *(unsigned long long*)(dsm + SM_Q + row * 512 + ((ch ^ rp) << 4) + sub) = uh;
    }
    __syncthreads();

    // ---- hoist Q fragments: 32 rows per warp (2 row-blocks of 16) ----
    const int rowA0 = wh * 32 + (lane & 15);
    const int cbA   = lane >> 4;
    const uint32_t aBase = sb + SM_Q + rowA0 * 512;
    const int rpA = rowA0 & 7;
    uint32_t qf[NKC][2][4];           // 128 regs
#pragma unroll
    for (int kc = 0; kc < NKC; kc++) {
        int offA = (((2 * kc + cbA) ^ rpA) << 4);
        LDSM_X4(qf[kc][0][0], qf[kc][0][1], qf[kc][0][2], qf[kc][0][3], aBase + offA);
        LDSM_X4(qf[kc][1][0], qf[kc][1][1], qf[kc][1][2], qf[kc][1][3], aBase + 8192 + offA);
    }
    __syncthreads();   // Q staging dead -> A1/A2 may be overwritten

    // ---- issue A tile 1 -> buffer 1 ----
    {
        const char* asrc = (const char*)g_aext + (size_t)NT * 1024;
#pragma unroll
        for (int i = 0; i < 8; i++) {
            int f = i * NTH + tid;
            int row = f >> 5, c = f & 31;
            uint32_t dst = sb + SM_A1 + row * 512 + ((c ^ (row & 7)) << 4);
            CP_ASYNC16(dst, asrc + (size_t)row * 1024 + c * 16);
        }
        CP_COMMIT();
    }

    // ---- B ldmatrix bases (this warp's 32-col half -> 2 n16-blocks) ----
    const int rowB = ((lane >> 4) * 8) + (lane & 7);
    const int ckB  = (lane >> 3) & 1;
    const int rpB  = rowB & 7;
    const uint32_t bOff0 = (uint32_t)(nh * 2) * 8192 + rowB * 512;       // p = nh*2
    const uint32_t bOff1 = (uint32_t)(nh * 2 + 1) * 8192 + rowB * 512;   // p = nh*2+1

    // per-(thread, row-slice) online softmax state; slices s = t*2+u
    float m2[4], s2[4], bv[4];
    int bi[4];
#pragma unroll
    for (int s = 0; s < 4; s++) { m2[s] = -1e30f; s2[s] = 0.f; bv[s] = -1e30f; bi[s] = 0x7fffffff; }

    int bcur = 0, bpre = 2;

#pragma unroll 1
    for (int nt = 0; nt < NTILES; nt++) {
        const int n0 = nt * NT;
        if (nt < NTILES - 1) { CP_WAIT1(); } else { CP_WAIT0(); }
        __syncthreads();

        if (nt + 2 < NTILES) {
            const char* asrc = (const char*)g_aext + (size_t)(n0 + 2 * NT) * 1024;
            const uint32_t dbuf = sb + SM_A0 + bpre * 32768;
#pragma unroll
            for (int i = 0; i < 8; i++) {
                int f = i * NTH + tid;
                int row = f >> 5, cc = f & 31;
                CP_ASYNC16(dbuf + row * 512 + ((cc ^ (row & 7)) << 4),
                           asrc + (size_t)row * 1024 + cc * 16);
            }
            CP_COMMIT();
        }

        const uint32_t bufBase = sb + SM_A0 + bcur * 32768;
        bcur = (bcur == 2) ? 0 : bcur + 1;
        bpre = (bpre == 2) ? 0 : bpre + 1;

        // ---- GEMM: 32 rows x 32 cols per warp over K=256 ----
        float c[2][4][4];
#pragma unroll
        for (int t = 0; t < 2; t++)
#pragma unroll
            for (int j = 0; j < 4; j++)
#pragma unroll
                for (int e = 0; e < 4; e++) c[t][j][e] = 0.f;

        uint32_t b[2][2][4];
        {
            int offB = ((ckB ^ rpB) << 4);
            LDSM_X4(b[0][0][0], b[0][0][1], b[0][0][2], b[0][0][3], bufBase + bOff0 + offB);
            LDSM_X4(b[0][1][0], b[0][1][1], b[0][1][2], b[0][1][3], bufBase + bOff1 + offB);
        }
#pragma unroll
        for (int kc = 0; kc < NKC; kc++) {
            const int cur = kc & 1, nxt = cur ^ 1;
            if (kc + 1 < NKC) {
                int offB = (((2 * (kc + 1) + ckB) ^ rpB) << 4);
                LDSM_X4(b[nxt][0][0], b[nxt][0][1], b[nxt][0][2], b[nxt][0][3], bufBase + bOff0 + offB);
                LDSM_X4(b[nxt][1][0], b[nxt][1][1], b[nxt][1][2], b[nxt][1][3], bufBase + bOff1 + offB);
            }
#pragma unroll
            for (int t = 0; t < 2; t++)
#pragma unroll
                for (int j = 0; j < 4; j++)
                    MMA16816(c[t][j], qf[kc][t][0], qf[kc][t][1], qf[kc][t][2], qf[kc][t][3],
                             b[cur][j >> 1][(j & 1) * 2], b[cur][j >> 1][(j & 1) * 2 + 1]);
        }

        // ---- epilogue: per-thread online softmax over own 8 cols/slice ----
        float ccr[4][2];
#pragma unroll
        for (int j = 0; j < 4; j++) {
            float2 cv = *(const float2*)(dsm + SM_CC + (size_t)(n0 + nh * 32 + j * 8 + qid * 2) * 4);
            ccr[j][0] = cv.x; ccr[j][1] = cv.y;
        }
#pragma unroll
        for (int s = 0; s < 4; s++) {
            const int t = s >> 1, u = s & 1;
            float lg[4][2];
            float mx = -1e30f;
#pragma unroll
            for (int j = 0; j < 4; j++) {
                lg[j][0] = fmaf(c[t][j][u * 2 + 0], SC2, ccr[j][0]);
                lg[j][1] = fmaf(c[t][j][u * 2 + 1], SC2, ccr[j][1]);
                mx = fmaxf(mx, fmaxf(lg[j][0], lg[j][1]));
            }
            if (mx > bv[s]) {   // strict > keeps earlier (first-max) winner
#pragma unroll
                for (int j = 0; j < 4; j++) {
                    int col0 = n0 + nh * 32 + j * 8 + qid * 2;
                    if (lg[j][0] > bv[s]) { bv[s] = lg[j][0]; bi[s] = col0; }
                    if (lg[j][1] > bv[s]) { bv[s] = lg[j][1]; bi[s] = col0 + 1; }
                }
            }
            if (mx > m2[s] - SKIP_THR) {
                float newm = fmaxf(m2[s], mx);
                float p = 0.f;
#pragma unroll
                for (int j = 0; j < 4; j++) { p += ex2f(lg[j][0] - newm); p += ex2f(lg[j][1] - newm); }
                s2[s] = fmaf(s2[s], ex2f(m2[s] - newm), p);
                m2[s] = newm;
            }
        }
    }

    // ---- quad merge, then cross-half merge via smem ----
    __syncthreads();   // all warps done with B buffers -> safe to alias A0
#pragma unroll
    for (int s = 0; s < 4; s++) {
        const int t = s >> 1, u = s & 1;
#pragma unroll
        for (int o = 1; o <= 2; o <<= 1) {
            float om = __shfl_xor_sync(0xFFFFFFFFu, m2[s], o);
            float os = __shfl_xor_sync(0xFFFFFFFFu, s2[s], o);
            float nm = fmaxf(m2[s], om);
            s2[s] = s2[s] * ex2f(m2[s] - nm) + os * ex2f(om - nm);
            m2[s] = nm;
            float ov = __shfl_xor_sync(0xFFFFFFFFu, bv[s], o);
            int   oi = __shfl_xor_sync(0xFFFFFFFFu, bi[s], o);
            if (ov > bv[s] || (ov == bv[s] && oi < bi[s])) { bv[s] = ov; bi[s] = oi; }
        }
        if (qid == 0) {
            int rl = wh * 32 + t * 16 + u * 8 + g;     // row within CTA
            ((float*)(dsm + SM_MRM))[rl * 2 + nh] = m2[s];
            ((float*)(dsm + SM_MRS))[rl * 2 + nh] = s2[s];
            ((float*)(dsm + SM_MBV))[rl * 2 + nh] = bv[s];
            ((int*)(dsm + SM_MBI))[rl * 2 + nh]   = bi[s];
        }
    }
    __syncthreads();

    if (tid < MT) {
        float ma = ((float*)(dsm + SM_MRM))[tid * 2], mb = ((float*)(dsm + SM_MRM))[tid * 2 + 1];
        float sa = ((float*)(dsm + SM_MRS))[tid * 2], sb2 = ((float*)(dsm + SM_MRS))[tid * 2 + 1];
        float M = fmaxf(ma, mb);
        float S = sa * ex2f(ma - M) + sb2 * ex2f(mb - M);
        float va = ((float*)(dsm + SM_MBV))[tid * 2], vb = ((float*)(dsm + SM_MBV))[tid * 2 + 1];
        int ia = ((int*)(dsm + SM_MBI))[tid * 2], ib = ((int*)(dsm + SM_MBI))[tid * 2 + 1];
        int BI = (vb > va || (vb == va && ib < ia)) ? ib : ia;
        ((float*)(dsm + SM_FM))[tid]  = M;
        ((float*)(dsm + SM_FS))[tid]  = S;
        ((int*)(dsm + SM_FBI))[tid]   = BI;
    }
    __syncthreads();

    // ---- exact label logit (hi+lo) + loss/prec accumulation in-block ----
    const int lab32 = g_lab32;
    double lsum = 0.0;
    int csum = 0;
#pragma unroll 2
    for (int it = 0; it < 16; it++) {
        int rl = wid * 16 + it;
        int r = r0 + rl;
        int ep = r >> 3;
        int lab = lab32 ? ((const int*)labraw)[ep] : (int)((const long long*)labraw)[ep];
        const float* q = x + ((size_t)ep * SLOTS + NS + (r & 7)) * D;
        const __half* a = g_aext + (size_t)lab * KEXT;
        int k = lane * 8;
        float4 q0 = *(const float4*)(q + k);
        float4 q1 = *(const float4*)(q + k + 4);
        uint4 uh = *(const uint4*)(a + k);
        uint4 ul = *(const uint4*)(a + 256 + k);
        const __half2* hh = (const __half2*)&uh;
        const __half2* hl = (const __half2*)&ul;
        float qq[8] = {q0.x, q0.y, q0.z, q0.w, q1.x, q1.y, q1.z, q1.w};
        float dot = 0.f;
#pragma unroll
        for (int i = 0; i < 4; i++) {
            float2 h = __half22float2(hh[i]);
            float2 l = __half22float2(hl[i]);
            dot = fmaf(qq[2 * i],     h.x + l.x, dot);
            dot = fmaf(qq[2 * i + 1], h.y + l.y, dot);
        }
#pragma unroll
        for (int o = 16; o; o >>= 1) dot += __shfl_xor_sync(0xFFFFFFFFu, dot, o);
        if (lane == 0) {
            float ll2 = fmaf(dot, SC2, ((const float*)(dsm + SM_CC))[lab]);
            float logp2 = ll2 - ((float*)(dsm + SM_FM))[rl] - lg2f(((float*)(dsm + SM_FS))[rl]);
            lsum += (double)logp2 * LN2;
            csum += (((int*)(dsm + SM_FBI))[rl] == lab) ? 1 : 0;
        }
    }
    if (lane == 0) { ((double*)(dsm + SM_SD))[wid] = lsum; ((int*)(dsm + SM_SI))[wid] = csum; }
    __syncthreads();
    if (tid == 0) {
        double ls = 0.0; int cs = 0;
#pragma unroll
        for (int i = 0; i < 8; i++) { ls += ((double*)(dsm + SM_SD))[i]; cs += ((int*)(dsm + SM_SI))[i]; }
        atomicAdd(&g_loss, ls);
        atomicAdd(&g_correct, cs);
    }
}

__global__ void final_kernel(float* out, int out_size) {
    if (out_size > 0) out[0] = (float)(-g_loss / (double)NROW);
    if (out_size > 1) out[1] = (float)g_correct * (100.0f / (float)NROW);
}

extern "C" void kernel_launch(void* const* d_in, const int* in_sizes, int n_in,
                              void* d_out, int out_size) {
    const float* x = (const float*)d_in[0];
    const unsigned long long* label = (const unsigned long long*)d_in[1];
    float* out = (float*)d_out;

    cudaFuncSetAttribute(gemm_softmax_kernel,
                         cudaFuncAttributeMaxDynamicSharedMemorySize, SMEM_BYTES);

    prep_kernel<<<N_EP, D>>>(x, label);
    gemm_softmax_kernel<<<NROW / MT, NTH, SMEM_BYTES>>>(x, (const void*)label);
    final_kernel<<<1, 1>>>(out, out_size);
}

// round 12
// speedup vs baseline: 1.1015x; 1.1015x over previous
#include <cuda_runtime.h>
#include <cuda_fp16.h>
#include <math.h>
#include <stdint.h>

// ---------------- problem constants ----------------
#define EPS    1e-6f
#define N_EP   2048
#define NS     5
#define SLOTS  13
#define D      256
#define NROW   16384
#define KEXT   512              // stored anchors: [hi(256) | lo(256)] fp16
#define MT     128              // M rows per CTA
#define NT     64               // N cols per tile
#define NTILES (N_EP / NT)      // 32
#define NKC    16               // k-steps of 16 over K=256 (hi only)
#define NTH    256
#define LOG2E  1.4426950408889634f
#define SC2    2.8853900817779268f   // 2*log2(e)
#define LN2    0.6931471805599453
#define SKIP_THR 24.0f
#define RBLKS  512              // reduce grid

// ---------------- device globals ----------------
__device__ __align__(256) __half g_aext[N_EP * KEXT];  // anchors split [n][512]
__device__ __align__(256) float  g_cc2[N_EP];          // (-a_sq + 2*eps*a_sum)*log2e
__device__ __align__(256) float  g_rowm[NROW];
__device__ __align__(256) float  g_rows[NROW];
__device__ __align__(256) int    g_rowbi[NROW];
__device__ double g_loss;
__device__ int    g_correct;
__device__ int    g_lab32;
__device__ unsigned g_tick;

// ---------------- smem layout (dynamic, bytes) ----------------
// B tiles are 64 rows x 512B = 32768 B (hi half only)
#define SM_CC    0          // 2048 floats = 8192
#define SM_A0    8192
#define SM_A1    40960
#define SM_A2    73728
#define SM_Q     40960      // Q staging (128 rows x 512B = 65536) aliases A1+A2
#define SMEM_BYTES 106496

// ---------------- PTX helpers (sm_80-level, portable to compute_103) --------
__device__ __forceinline__ uint32_t smem_u32(const void* p) {
    uint32_t a;
    asm("{ .reg .u64 t; cvta.to.shared.u64 t, %1; cvt.u32.u64 %0, t; }" : "=r"(a) : "l"(p));
    return a;
}
#define CP_ASYNC16(dst, src) \
    asm volatile("cp.async.cg.shared.global [%0], [%1], 16;" :: "r"(dst), "l"(src) : "memory")
#define CP_COMMIT() asm volatile("cp.async.commit_group;" ::: "memory")
#define CP_WAIT0()  asm volatile("cp.async.wait_group 0;" ::: "memory")
#define CP_WAIT1()  asm volatile("cp.async.wait_group 1;" ::: "memory")

#define LDSM_X4(r0, r1, r2, r3, addr) \
    asm volatile("ldmatrix.sync.aligned.m8n8.x4.shared.b16 {%0,%1,%2,%3}, [%4];" \
        : "=r"(r0), "=r"(r1), "=r"(r2), "=r"(r3) : "r"(addr))

#define MMA16816(c, a0, a1, a2, a3, b0, b1) \
    asm volatile("mma.sync.aligned.m16n8k16.row.col.f32.f16.f16.f32 " \
        "{%0,%1,%2,%3}, {%4,%5,%6,%7}, {%8,%9}, {%0,%1,%2,%3};" \
        : "+f"((c)[0]), "+f"((c)[1]), "+f"((c)[2]), "+f"((c)[3]) \
        : "r"(a0), "r"(a1), "r"(a2), "r"(a3), "r"(b0), "r"(b1))

__device__ __forceinline__ float ex2f(float x) { float r; asm("ex2.approx.f32 %0, %1;" : "=f"(r) : "f"(x)); return r; }
__device__ __forceinline__ float lg2f(float x) { float r; asm("lg2.approx.f32 %0, %1;" : "=f"(r) : "f"(x)); return r; }

// ---------------- prep: warp-per-episode anchor split + column constant -----
// 256 blocks x 256 threads; warp w handles episode blockIdx*8+w; lane owns 8 dims.
__global__ void prep_kernel(const float* __restrict__ x,
                            const unsigned long long* __restrict__ lab) {
    const int lane = threadIdx.x & 31, w = threadIdx.x >> 5;
    const int ep = blockIdx.x * 8 + w;
    if (blockIdx.x == 0 && threadIdx.x < 32) {     // folded init + label sniff
        unsigned long long v = lab[threadIdx.x];
        unsigned b = __ballot_sync(0xFFFFFFFFu, (v >> 32) != 0ull);
        if (threadIdx.x == 0) {
            g_loss = 0.0; g_correct = 0; g_tick = 0u;
            g_lab32 = (b != 0u) ? 1 : 0;
        }
    }
    const float* xr = x + (size_t)ep * SLOTS * D + lane * 8;
    float a[8];
#pragma unroll
    for (int h = 0; h < 2; h++) {
        float4 v0 = *(const float4*)(xr + h * 4);
        a[h * 4 + 0] = v0.x; a[h * 4 + 1] = v0.y; a[h * 4 + 2] = v0.z; a[h * 4 + 3] = v0.w;
    }
#pragma unroll
    for (int s = 1; s < NS; s++) {
#pragma unroll
        for (int h = 0; h < 2; h++) {
            float4 v = *(const float4*)(xr + s * D + h * 4);
            a[h * 4 + 0] += v.x; a[h * 4 + 1] += v.y; a[h * 4 + 2] += v.z; a[h * 4 + 3] += v.w;
        }
    }
    float sq = 0.f, sm = 0.f;
    __half2 hi2[4], lo2[4];
#pragma unroll
    for (int i = 0; i < 8; i++) {
        a[i] *= 0.2f;
        sq = fmaf(a[i], a[i], sq);
        sm += a[i];
    }
#pragma unroll
    for (int i = 0; i < 4; i++) {
        __half h0 = __float2half_rn(a[2 * i]), h1 = __float2half_rn(a[2 * i + 1]);
        __half l0 = __float2half_rn(a[2 * i] - __half2float(h0));
        __half l1 = __float2half_rn(a[2 * i + 1] - __half2float(h1));
        hi2[i] = __halves2half2(h0, h1);
        lo2[i] = __halves2half2(l0, l1);
    }
    *(uint4*)(g_aext + (size_t)ep * KEXT + lane * 8)       = *(uint4*)hi2;
    *(uint4*)(g_aext + (size_t)ep * KEXT + 256 + lane * 8) = *(uint4*)lo2;
#pragma unroll
    for (int o = 16; o; o >>= 1) {
        sq += __shfl_xor_sync(0xFFFFFFFFu, sq, o);
        sm += __shfl_xor_sync(0xFFFFFFFFu, sm, o);
    }
    if (lane == 0) g_cc2[ep] = (-sq + 2.0f * EPS * sm) * LOG2E;
}

// ---------------- fused HMMA GEMM (K=256, hi-only) + online softmax ----------
extern __shared__ char dsm[];

__global__ void __launch_bounds__(NTH, 1) gemm_softmax_kernel(const float* __restrict__ x) {
    const uint32_t sb = smem_u32(dsm);
    const int tid = threadIdx.x, wid = tid >> 5, lane = tid & 31;
    const int qid = lane & 3;
    const int r0 = blockIdx.x * MT;

    // ---- issue A tile 0 early (buffer 0 is independent of Q staging) ----
    {
        const char* asrc = (const char*)g_aext;        // row stride 1024B; hi = first 512B
#pragma unroll
        for (int i = 0; i < 8; i++) {
            int f = i * NTH + tid;                     // 64 rows x 32 16B-chunks
            int row = f >> 5, c = f & 31;
            uint32_t dst = sb + SM_A0 + row * 512 + ((c ^ (row & 7)) << 4);
            CP_ASYNC16(dst, asrc + (size_t)row * 1024 + c * 16);
        }
        CP_COMMIT();
    }

    // ---- stage column constants ----
#pragma unroll
    for (int i = tid; i < N_EP / 4; i += NTH)
        ((float4*)(dsm + SM_CC))[i] = ((const float4*)g_cc2)[i];

    // ---- stage Q tile (fp32 -> fp16 hi only, 512B XOR-swizzled rows) ----
#pragma unroll 2
    for (int i = 0; i < 32; i++) {
        int f = i * NTH + tid;            // 128 rows x 64 float4-segments
        int row = f >> 6, seg = f & 63;
        int r = r0 + row;
        const float4 v = *(const float4*)(x + ((size_t)(r >> 3) * SLOTS + NS + (r & 7)) * D + seg * 4);
        __half2 ph01 = __halves2half2(__float2half_rn(v.x), __float2half_rn(v.y));
        __half2 ph23 = __halves2half2(__float2half_rn(v.z), __float2half_rn(v.w));
        unsigned long long uh = ((unsigned long long)(*(uint32_t*)&ph23) << 32) | (*(uint32_t*)&ph01);
        int rp = row & 7;
        int ch = seg >> 1;                 // chunk 0..31
        int sub = (seg & 1) * 8;
        *(unsigned long long*)(dsm + SM_Q + row * 512 + ((ch ^ rp) << 4) + sub) = uh;
    }
    __syncthreads();

    // ---- hoist Q fragments to registers (64 regs; never re-read) ----
    const int rowA = wid * 16 + (lane & 15);
    const int cbA  = lane >> 4;
    const uint32_t aBase = sb + SM_Q + rowA * 512;
    const int rpA = rowA & 7;
    uint32_t qf[NKC][4];
#pragma unroll
    for (int kc = 0; kc < NKC; kc++) {
        int offA = (((2 * kc + cbA) ^ rpA) << 4);
        LDSM_X4(qf[kc][0], qf[kc][1], qf[kc][2], qf[kc][3], aBase + offA);
    }
    __syncthreads();   // Q staging dead -> A1/A2 may be overwritten

    // ---- issue A tile 1 -> buffer 1 ----
    {
        const char* asrc = (const char*)g_aext + (size_t)NT * 1024;
#pragma unroll
        for (int i = 0; i < 8; i++) {
            int f = i * NTH + tid;
            int row = f >> 5, c = f & 31;
            uint32_t dst = sb + SM_A1 + row * 512 + ((c ^ (row & 7)) << 4);
            CP_ASYNC16(dst, asrc + (size_t)row * 1024 + c * 16);
        }
        CP_COMMIT();
    }

    // ---- B ldmatrix bases ----
    const int rowB = ((lane >> 4) * 8) + (lane & 7);
    const int ckB  = (lane >> 3) & 1;
    const int rpB  = rowB & 7;

    float m2[2], s2[2], bv[2];
    int bi[2];
#pragma unroll
    for (int s = 0; s < 2; s++) { m2[s] = -1e30f; s2[s] = 0.f; bv[s] = -1e30f; bi[s] = 0x7fffffff; }

    int bcur = 0, bpre = 2;

#pragma unroll 1
    for (int nt = 0; nt < NTILES; nt++) {
        const int n0 = nt * NT;
        if (nt < NTILES - 1) { CP_WAIT1(); } else { CP_WAIT0(); }
        __syncthreads();      // tile nt visible; all warps done with tile nt-1

        // refill: tile nt+2 into the buffer freed by tile nt-1
        if (nt + 2 < NTILES) {
            const char* asrc = (const char*)g_aext + (size_t)(n0 + 2 * NT) * 1024;
            const uint32_t dbuf = sb + SM_A0 + bpre * 32768;
#pragma unroll
            for (int i = 0; i < 8; i++) {
                int f = i * NTH + tid;
                int row = f >> 5, cc = f & 31;
                CP_ASYNC16(dbuf + row * 512 + ((cc ^ (row & 7)) << 4),
                           asrc + (size_t)row * 1024 + cc * 16);
            }
            CP_COMMIT();
        }

        const uint32_t bufB = sb + SM_A0 + bcur * 32768 + rowB * 512;
        bcur = (bcur == 2) ? 0 : bcur + 1;
        bpre = (bpre == 2) ? 0 : bpre + 1;

        // ---- GEMM: 16 rows x 64 cols per warp over K=256, B double-buffered ----
        float c[8][4];
#pragma unroll
        for (int j = 0; j < 8; j++)
#pragma unroll
            for (int e = 0; e < 4; e++) c[j][e] = 0.f;

        uint32_t b[2][4][4];
        {
            int offB = ((ckB ^ rpB) << 4);
#pragma unroll
            for (int p = 0; p < 4; p++)
                LDSM_X4(b[0][p][0], b[0][p][1], b[0][p][2], b[0][p][3], bufB + p * 8192 + offB);
        }
#pragma unroll
        for (int kc = 0; kc < NKC; kc++) {
            const int cur = kc & 1, nxt = cur ^ 1;
            if (kc + 1 < NKC) {
                int offB = (((2 * (kc + 1) + ckB) ^ rpB) << 4);
#pragma unroll
                for (int p = 0; p < 4; p++)
                    LDSM_X4(b[nxt][p][0], b[nxt][p][1], b[nxt][p][2], b[nxt][p][3],
                            bufB + p * 8192 + offB);
            }
#pragma unroll
            for (int j = 0; j < 8; j++)
                MMA16816(c[j], qf[kc][0], qf[kc][1], qf[kc][2], qf[kc][3],
                         b[cur][j >> 1][(j & 1) * 2], b[cur][j >> 1][(j & 1) * 2 + 1]);
        }

        // ---- epilogue: shared cc loads, per-slice skip guards ----
        float lg0[8][2], lg1[8][2];
        float mx0 = -1e30f, mx1 = -1e30f;
#pragma unroll
        for (int j = 0; j < 8; j++) {
            float2 cv = *(const float2*)(dsm + SM_CC + (size_t)(n0 + j * 8 + qid * 2) * 4);
            lg0[j][0] = fmaf(c[j][0], SC2, cv.x);
            lg0[j][1] = fmaf(c[j][1], SC2, cv.y);
            lg1[j][0] = fmaf(c[j][2], SC2, cv.x);
            lg1[j][1] = fmaf(c[j][3], SC2, cv.y);
            mx0 = fmaxf(mx0, fmaxf(lg0[j][0], lg0[j][1]));
            mx1 = fmaxf(mx1, fmaxf(lg1[j][0], lg1[j][1]));
        }
        if (mx0 > bv[0]) {
#pragma unroll
            for (int j = 0; j < 8; j++) {
                int col0 = n0 + j * 8 + qid * 2;
                if (lg0[j][0] > bv[0]) { bv[0] = lg0[j][0]; bi[0] = col0; }
                if (lg0[j][1] > bv[0]) { bv[0] = lg0[j][1]; bi[0] = col0 + 1; }
            }
        }
        if (mx0 > m2[0] - SKIP_THR) {
            float newm = fmaxf(m2[0], mx0);
            float p = 0.f;
#pragma unroll
            for (int j = 0; j < 8; j++) { p += ex2f(lg0[j][0] - newm); p += ex2f(lg0[j][1] - newm); }
            s2[0] = fmaf(s2[0], ex2f(m2[0] - newm), p);
            m2[0] = newm;
        }
        if (mx1 > bv[1]) {
#pragma unroll
            for (int j = 0; j < 8; j++) {
                int col0 = n0 + j * 8 + qid * 2;
                if (lg1[j][0] > bv[1]) { bv[1] = lg1[j][0]; bi[1] = col0; }
                if (lg1[j][1] > bv[1]) { bv[1] = lg1[j][1]; bi[1] = col0 + 1; }
            }
        }
        if (mx1 > m2[1] - SKIP_THR) {
            float newm = fmaxf(m2[1], mx1);
            float p = 0.f;
#pragma unroll
            for (int j = 0; j < 8; j++) { p += ex2f(lg1[j][0] - newm); p += ex2f(lg1[j][1] - newm); }
            s2[1] = fmaf(s2[1], ex2f(m2[1] - newm), p);
            m2[1] = newm;
        }
    }

    // ---- final cross-quad merge + per-row global writeout ----
#pragma unroll
    for (int s = 0; s < 2; s++) {
#pragma unroll
        for (int o = 1; o <= 2; o <<= 1) {
            float om = __shfl_xor_sync(0xFFFFFFFFu, m2[s], o);
            float os = __shfl_xor_sync(0xFFFFFFFFu, s2[s], o);
            float nm = fmaxf(m2[s], om);
            s2[s] = s2[s] * ex2f(m2[s] - nm) + os * ex2f(om - nm);
            m2[s] = nm;
            float ov = __shfl_xor_sync(0xFFFFFFFFu, bv[s], o);
            int   oi = __shfl_xor_sync(0xFFFFFFFFu, bi[s], o);
            if (ov > bv[s] || (ov == bv[s] && oi < bi[s])) { bv[s] = ov; bi[s] = oi; }
        }
        if (qid == 0) {
            int row = r0 + wid * 16 + (lane >> 2) + s * 8;
            g_rowm[row]  = m2[s];
            g_rows[row]  = s2[s];
            g_rowbi[row] = bi[s];
        }
    }
}

// ---------------- reduce: exact label logit; final fold via ticket ----------
__global__ void reduce_kernel(const float* __restrict__ x, const void* __restrict__ labraw,
                              float* __restrict__ out, int out_size) {
    const int tid = threadIdx.x, lane = tid & 31, w = tid >> 5;
    const int lab32 = g_lab32;
    __shared__ double sd[8];
    __shared__ int    si[8];
    __shared__ unsigned slast;

    double lsum = 0.0;
    int csum = 0;
    const int rbase = blockIdx.x * 32 + w * 4;
#pragma unroll
    for (int it = 0; it < 4; it++) {
        int r = rbase + it;
        int ep = r >> 3;
        int lab = lab32 ? ((const int*)labraw)[ep] : (int)((const long long*)labraw)[ep];
        const float* q = x + ((size_t)ep * SLOTS + NS + (r & 7)) * D;
        const __half* a = g_aext + (size_t)lab * KEXT;
        int k = lane * 8;
        float4 q0 = *(const float4*)(q + k);
        float4 q1 = *(const float4*)(q + k + 4);
        uint4 uh = *(const uint4*)(a + k);
        uint4 ul = *(const uint4*)(a + 256 + k);
        const __half2* hh = (const __half2*)&uh;
        const __half2* hl = (const __half2*)&ul;
        float qq[8] = {q0.x, q0.y, q0.z, q0.w, q1.x, q1.y, q1.z, q1.w};
        float dot = 0.f;
#pragma unroll
        for (int i = 0; i < 4; i++) {
            float2 h = __half22float2(hh[i]);
            float2 l = __half22float2(hl[i]);
            dot = fmaf(qq[2 * i],     h.x + l.x, dot);
            dot = fmaf(qq[2 * i + 1], h.y + l.y, dot);
        }
#pragma unroll
        for (int o = 16; o; o >>= 1) dot += __shfl_xor_sync(0xFFFFFFFFu, dot, o);
        if (lane == 0) {
            float ll2 = fmaf(dot, SC2, g_cc2[lab]);
            float logp2 = ll2 - g_rowm[r] - lg2f(g_rows[r]);
            lsum += (double)logp2 * LN2;
            csum += (g_rowbi[r] == lab) ? 1 : 0;
        }
    }
    if (lane == 0) { sd[w] = lsum; si[w] = csum; }
    __syncthreads();
    if (tid == 0) {
        double ls = 0.0; int cs = 0;
#pragma unroll
        for (int i = 0; i < 8; i++) { ls += sd[i]; cs += si[i]; }
        atomicAdd(&g_loss, ls);
        atomicAdd(&g_correct, cs);
        __threadfence();
        slast = atomicAdd(&g_tick, 1u);
    }
    __syncthreads();
    if (slast == RBLKS - 1 && tid == 0) {    // last block finalizes output
        __threadfence();
        if (out_size > 0) out[0] = (float)(-g_loss / (double)NROW);
        if (out_size > 1) out[1] = (float)g_correct * (100.0f / (float)NROW);
    }
}

extern "C" void kernel_launch(void* const* d_in, const int* in_sizes, int n_in,
                              void* d_out, int out_size) {
    const float* x = (const float*)d_in[0];
    const unsigned long long* label = (const unsigned long long*)d_in[1];
    float* out = (float*)d_out;

    cudaFuncSetAttribute(gemm_softmax_kernel,
                         cudaFuncAttributeMaxDynamicSharedMemorySize, SMEM_BYTES);

    prep_kernel<<<N_EP / 8, 256>>>(x, label);
    gemm_softmax_kernel<<<NROW / MT, NTH, SMEM_BYTES>>>(x);
    reduce_kernel<<<RBLKS, 256>>>(x, (const void*)label, out, out_size);
}